// round 1
// baseline (speedup 1.0000x reference)
#include <cuda_runtime.h>
#include <mma.h>
#include <math.h>

using namespace nvcuda;

#define NE 8
#define NT 2048
#define NH 2048
#define NI 4096
#define TWO_I 8192
#define NSLOT (2*NT)

// ---------------- scratch (device globals; no allocation APIs) ----------------
__device__ int   g_cnt[NE];
__device__ int   g_rows[NE * NT];           // row_id = 2*t + k assigned to expert e
__device__ float g_gw[NSLOT];               // gating weight per row_id
__device__ float g_h [(size_t)NSLOT * TWO_I]; // GEMM1 output (gate|up), 128MB
__device__ float g_i [(size_t)NSLOT * NI];    // silu(gate)*up, 64MB

// ---------------- misc kernels ----------------
__global__ void k_zero_cnt() {
    if (threadIdx.x < NE) g_cnt[threadIdx.x] = 0;
}

// ---------------- router + sparsemixer ----------------
__global__ void k_router(const float* __restrict__ x, const float* __restrict__ gw) {
    int t = blockIdx.x;
    int warp = threadIdx.x >> 5, lane = threadIdx.x & 31;
    __shared__ float s[NE];
    const float* xr = x + (size_t)t * NH;
    const float* we = gw + (size_t)warp * NH;
    float acc = 0.f;
    for (int k = lane; k < NH; k += 32) acc += xr[k] * we[k];
    #pragma unroll
    for (int o = 16; o; o >>= 1) acc += __shfl_xor_sync(0xffffffffu, acc, o);
    if (lane == 0) s[warp] = acc;
    __syncthreads();
    if (threadIdx.x == 0) {
        float sc[NE];
        #pragma unroll
        for (int e = 0; e < NE; e++) sc[e] = s[e];

        // pass 1
        float mx1 = -INFINITY; int i1 = 0;
        #pragma unroll
        for (int e = 0; e < NE; e++) if (sc[e] > mx1) { mx1 = sc[e]; i1 = e; }
        float sum1 = 0.f;
        #pragma unroll
        for (int e = 0; e < NE; e++) {
            float f = fmaxf(fabsf(sc[e]), mx1);
            bool masked = ((mx1 - sc[e]) / f) > 0.02f;
            if (!masked) sum1 += expf(sc[e] - mx1);
        }
        float g1 = 1.f / sum1;

        // pass 2 (exclude i1)
        float mx2 = -INFINITY; int i2 = 0;
        #pragma unroll
        for (int e = 0; e < NE; e++) if (e != i1 && sc[e] > mx2) { mx2 = sc[e]; i2 = e; }
        float sum2 = 0.f;
        #pragma unroll
        for (int e = 0; e < NE; e++) {
            if (e == i1) continue;
            float f = fmaxf(fabsf(sc[e]), mx2);
            bool masked = ((mx2 - sc[e]) / f) > 0.02f;
            if (!masked) sum2 += expf(sc[e] - mx2);
        }
        float g2 = 1.f / sum2;

        int p1 = atomicAdd(&g_cnt[i1], 1);
        g_rows[i1 * NT + p1] = 2 * t;
        g_gw[2 * t] = g1;
        int p2 = atomicAdd(&g_cnt[i2], 1);
        g_rows[i2 * NT + p2] = 2 * t + 1;
        g_gw[2 * t + 1] = g2;
    }
}

// ---------------- grouped GEMM (tf32 wmma), NT layout: A[M,K] row-major gathered, B[N,K] row-major ----------------
// MODE 1: A = x (row = row_id>>1, K=NH), B = ws[e] [8192,2048], C = g_h rows (row_id)
// MODE 2: A = g_i (row = row_id,   K=NI), B = w2s[e] [2048,4096], C = atomicAdd into out scaled by g_gw
constexpr int BM = 128, BN = 128, BK = 16, KPAD = 24, CLD = BN + 4;
constexpr int SMEM_BYTES = BM * CLD * 4; // 67584; also covers As+Bs (24576)

template<int MODE>
__global__ void __launch_bounds__(256) k_gemm(const float* __restrict__ Aarg,
                                              const float* __restrict__ Barg,
                                              float* __restrict__ Carg) {
    constexpr int K = (MODE == 1) ? NH : NI;
    constexpr int N = (MODE == 1) ? TWO_I : NH;

    int e = blockIdx.z;
    int cnt = g_cnt[e];
    int m0 = blockIdx.x * BM;
    if (m0 >= cnt) return;
    int n0 = blockIdx.y * BN;

    extern __shared__ float smem[];
    float* As = smem;              // BM*KPAD
    float* Bs = smem + BM * KPAD;  // BN*KPAD
    __shared__ int rowids[BM];

    int tid = threadIdx.x;
    if (tid < BM) {
        int m = m0 + tid;
        rowids[tid] = (m < cnt) ? g_rows[e * NT + tid + (m0)] : -1;
    }
    __syncthreads();

    const float* A = (MODE == 1) ? Aarg : (const float*)g_i;
    const float* Bexp = Barg + (size_t)e * N * K;

    int warp = tid >> 5;
    int wm = warp & 1;   // 0..1 -> 64-row subtile
    int wn = warp >> 1;  // 0..3 -> 32-col subtile

    wmma::fragment<wmma::accumulator, 16, 16, 8, float> acc[4][2];
    #pragma unroll
    for (int fm = 0; fm < 4; fm++)
        #pragma unroll
        for (int fn = 0; fn < 2; fn++)
            wmma::fill_fragment(acc[fm][fn], 0.f);

    int lr = tid >> 2, lq = tid & 3;  // loader mapping: rows lr, lr+64; float4 chunk lq
    int r0 = rowids[lr], r1 = rowids[lr + 64];
    bool v0 = (r0 >= 0), v1 = (r1 >= 0);
    size_t ar0 = (size_t)(v0 ? ((MODE == 1) ? (r0 >> 1) : r0) : 0) * K;
    size_t ar1 = (size_t)(v1 ? ((MODE == 1) ? (r1 >> 1) : r1) : 0) * K;
    const float4 zero4 = make_float4(0.f, 0.f, 0.f, 0.f);

    for (int kb = 0; kb < K; kb += BK) {
        float4 av0 = v0 ? *(const float4*)(A + ar0 + kb + lq * 4) : zero4;
        float4 av1 = v1 ? *(const float4*)(A + ar1 + kb + lq * 4) : zero4;
        float4 bv0 = *(const float4*)(Bexp + (size_t)(n0 + lr) * K + kb + lq * 4);
        float4 bv1 = *(const float4*)(Bexp + (size_t)(n0 + lr + 64) * K + kb + lq * 4);
        *(float4*)(As + lr * KPAD + lq * 4) = av0;
        *(float4*)(As + (lr + 64) * KPAD + lq * 4) = av1;
        *(float4*)(Bs + lr * KPAD + lq * 4) = bv0;
        *(float4*)(Bs + (lr + 64) * KPAD + lq * 4) = bv1;
        __syncthreads();

        #pragma unroll
        for (int kk = 0; kk < BK; kk += 8) {
            wmma::fragment<wmma::matrix_a, 16, 16, 8, wmma::precision::tf32, wmma::row_major> af[4];
            wmma::fragment<wmma::matrix_b, 16, 16, 8, wmma::precision::tf32, wmma::col_major> bf[2];
            #pragma unroll
            for (int fm = 0; fm < 4; fm++) {
                wmma::load_matrix_sync(af[fm], As + (wm * 64 + fm * 16) * KPAD + kk, KPAD);
                #pragma unroll
                for (int u = 0; u < af[fm].num_elements; u++)
                    af[fm].x[u] = wmma::__float_to_tf32(af[fm].x[u]);
            }
            #pragma unroll
            for (int fn = 0; fn < 2; fn++) {
                wmma::load_matrix_sync(bf[fn], Bs + (wn * 32 + fn * 16) * KPAD + kk, KPAD);
                #pragma unroll
                for (int u = 0; u < bf[fn].num_elements; u++)
                    bf[fn].x[u] = wmma::__float_to_tf32(bf[fn].x[u]);
            }
            #pragma unroll
            for (int fm = 0; fm < 4; fm++)
                #pragma unroll
                for (int fn = 0; fn < 2; fn++)
                    wmma::mma_sync(acc[fm][fn], af[fm], bf[fn], acc[fm][fn]);
        }
        __syncthreads();
    }

    // epilogue: stage tile to shared (reuse As/Bs region), then scattered writes
    float* Cs = smem;
    #pragma unroll
    for (int fm = 0; fm < 4; fm++)
        #pragma unroll
        for (int fn = 0; fn < 2; fn++)
            wmma::store_matrix_sync(Cs + (size_t)(wm * 64 + fm * 16) * CLD + wn * 32 + fn * 16,
                                    acc[fm][fn], CLD, wmma::mem_row_major);
    __syncthreads();

    int r = tid >> 1;
    int ch = (tid & 1) * 64;
    int rid = rowids[r];
    if (rid >= 0) {
        const float* src = Cs + (size_t)r * CLD + ch;
        if (MODE == 1) {
            float* dst = g_h + (size_t)rid * TWO_I + n0 + ch;
            #pragma unroll
            for (int c = 0; c < 64; c += 4)
                *(float4*)(dst + c) = *(const float4*)(src + c);
        } else {
            float g = g_gw[rid];
            int tok = rid >> 1;
            float* dst = Carg + (size_t)tok * NH + n0 + ch;
            #pragma unroll
            for (int c = 0; c < 64; c++)
                atomicAdd(dst + c, g * src[c]);
        }
    }
}

// ---------------- silu(gate) * up ----------------
__global__ void k_silu() {
    size_t idx = (size_t)blockIdx.x * blockDim.x + threadIdx.x;
    size_t total = (size_t)NSLOT * NI / 4;
    if (idx >= total) return;
    size_t r = idx / (NI / 4);
    size_t c = (idx % (NI / 4)) * 4;
    float4 gv = *(const float4*)(g_h + r * TWO_I + c);
    float4 uv = *(const float4*)(g_h + r * TWO_I + NI + c);
    float4 o;
    o.x = gv.x / (1.f + expf(-gv.x)) * uv.x;
    o.y = gv.y / (1.f + expf(-gv.y)) * uv.y;
    o.z = gv.z / (1.f + expf(-gv.z)) * uv.z;
    o.w = gv.w / (1.f + expf(-gv.w)) * uv.w;
    *(float4*)(g_i + r * NI + c) = o;
}

// ---------------- launch ----------------
extern "C" void kernel_launch(void* const* d_in, const int* in_sizes, int n_in,
                              void* d_out, int out_size) {
    const float* x     = (const float*)d_in[0];
    const float* gatew = (const float*)d_in[1];
    const float* ws    = (const float*)d_in[2];
    const float* w2s   = (const float*)d_in[3];
    float* out = (float*)d_out;

    cudaFuncSetAttribute((const void*)k_gemm<1>, cudaFuncAttributeMaxDynamicSharedMemorySize, SMEM_BYTES);
    cudaFuncSetAttribute((const void*)k_gemm<2>, cudaFuncAttributeMaxDynamicSharedMemorySize, SMEM_BYTES);

    cudaMemsetAsync(d_out, 0, (size_t)out_size * sizeof(float), 0);
    k_zero_cnt<<<1, 32>>>();
    k_router<<<NT, 256>>>(x, gatew);

    dim3 g1(NT / BM, TWO_I / BN, NE);
    k_gemm<1><<<g1, 256, SMEM_BYTES>>>(x, ws, nullptr);

    k_silu<<<(int)(((size_t)NSLOT * NI / 4 + 255) / 256), 256>>>();

    dim3 g2(NT / BM, NH / BN, NE);
    k_gemm<2><<<g2, 256, SMEM_BYTES>>>(nullptr, w2s, out);
}